// round 16
// baseline (speedup 1.0000x reference)
#include <cuda_runtime.h>
#include <cuda_fp16.h>
#include <stdint.h>

#define N_TOT   131072
#define C_DIM   512
#define H_NUM   8
#define P_NUM   1024
#define C3      1536
#define RPE_MAX 33

static __device__ __half g_qkv [(size_t)N_TOT * C3];     // stage1 out (half)
static __device__ __half g_ao  [(size_t)N_TOT * C_DIM];  // attn out (half)
static __device__ __half g_w1  [(size_t)C3 * C_DIM];     // qkv_w half
static __device__ __half g_w3  [(size_t)C_DIM * C_DIM];  // proj_w half

// ---------------------------------------------------------------- helpers --
__device__ __forceinline__ uint32_t sptr(const void* p) {
    return (uint32_t)__cvta_generic_to_shared(p);
}
__device__ __forceinline__ void ldsm_x4(uint32_t& r0, uint32_t& r1,
                                        uint32_t& r2, uint32_t& r3, uint32_t addr) {
    asm volatile("ldmatrix.sync.aligned.m8n8.x4.shared.b16 {%0,%1,%2,%3}, [%4];"
                 : "=r"(r0), "=r"(r1), "=r"(r2), "=r"(r3) : "r"(addr));
}
__device__ __forceinline__ void ldsm_x4t(uint32_t& r0, uint32_t& r1,
                                         uint32_t& r2, uint32_t& r3, uint32_t addr) {
    asm volatile("ldmatrix.sync.aligned.m8n8.x4.trans.shared.b16 {%0,%1,%2,%3}, [%4];"
                 : "=r"(r0), "=r"(r1), "=r"(r2), "=r"(r3) : "r"(addr));
}
__device__ __forceinline__ void mma_f16(float* d,
                                        uint32_t a0, uint32_t a1, uint32_t a2, uint32_t a3,
                                        uint32_t b0, uint32_t b1)
{
    asm volatile(
        "mma.sync.aligned.m16n8k16.row.col.f32.f16.f16.f32 "
        "{%0,%1,%2,%3}, {%4,%5,%6,%7}, {%8,%9}, {%0,%1,%2,%3};"
        : "+f"(d[0]), "+f"(d[1]), "+f"(d[2]), "+f"(d[3])
        : "r"(a0), "r"(a1), "r"(a2), "r"(a3), "r"(b0), "r"(b1));
}
__device__ __forceinline__ uint32_t pkh2(float lo, float hi) {
    __half2 h = __floats2half2_rn(lo, hi);
    return *(uint32_t*)&h;
}
__device__ __forceinline__ void cpa16(uint32_t dst, const void* src) {
    asm volatile("cp.async.cg.shared.global [%0], [%1], 16;"
                 :: "r"(dst), "l"(src) : "memory");
}
__device__ __forceinline__ void cpa_commit() {
    asm volatile("cp.async.commit_group;" ::: "memory");
}
__device__ __forceinline__ void cpa_wait1() {
    asm volatile("cp.async.wait_group 1;" ::: "memory");
}
__device__ __forceinline__ void cpa_wait0() {
    asm volatile("cp.async.wait_group 0;" ::: "memory");
}
__device__ __forceinline__ void sts128(uint32_t addr, uint32_t a, uint32_t b,
                                       uint32_t c, uint32_t d) {
    asm volatile("st.shared.v4.b32 [%0], {%1,%2,%3,%4};"
                 :: "r"(addr), "r"(a), "r"(b), "r"(c), "r"(d) : "memory");
}

// ---------------------------------------------------------------------------
// Pre-pass: weight cvt to fp16 (qkv_w then proj_w, one grid)
// ---------------------------------------------------------------------------
__global__ __launch_bounds__(256) void cvt_weights(
    const float* __restrict__ w1_in, const float* __restrict__ w3_in,
    __half* __restrict__ w1_out, __half* __restrict__ w3_out)
{
    const size_t n1 = (size_t)C3 * C_DIM / 8;
    size_t idx = (size_t)blockIdx.x * 256 + threadIdx.x;
    const float* fp;
    __half* op;
    if (idx < n1) { fp = w1_in + idx * 8; op = w1_out + idx * 8; }
    else          { fp = w3_in + (idx - n1) * 8; op = w3_out + (idx - n1) * 8; }
    float4 v0 = *(const float4*)(fp);
    float4 v1 = *(const float4*)(fp + 4);
    __half h[8];
    h[0]=__float2half_rn(v0.x); h[1]=__float2half_rn(v0.y);
    h[2]=__float2half_rn(v0.z); h[3]=__float2half_rn(v0.w);
    h[4]=__float2half_rn(v1.x); h[5]=__float2half_rn(v1.y);
    h[6]=__float2half_rn(v1.z); h[7]=__float2half_rn(v1.w);
    *(uint4*)op = *(uint4*)h;
}

// ---------------------------------------------------------------------------
// FP16 mma.sync GEMM (NT), fp32 accum. Block 256m x 128n, BK=64, 512 threads.
// A_F32=1: A is fp32 with gather index gidx; fill does LDG+cvt+STS (fused
// gather — no prepass). A_F32=0: A is half, fill via cp.async.
// ---------------------------------------------------------------------------
#define ROWB     144
#define A_BYTES  (256 * ROWB)
#define B_BYTES  (128 * ROWB)
#define STG      (A_BYTES + B_BYTES)
#define NSTAGE   3
#define DYN_SMEM (NSTAGE * STG)           // 165888

template<int OUT_HALF, int A_F32>
__global__ __launch_bounds__(512, 1) void gemm_h(
    const void* __restrict__ Av, const __half* __restrict__ W,
    const float* __restrict__ bias, void* __restrict__ outv,
    const int* __restrict__ gidx, const int* __restrict__ sidx,
    int Ncols, int Kd)
{
    extern __shared__ char dyn[];
    const uint32_t sbase = sptr(dyn);

    const int t = threadIdx.x;
    const int warp = t >> 5;
    const int lane = t & 31;
    const int wm = warp & 3;
    const int wn = warp >> 2;
    const int m0 = blockIdx.y * 256;
    const int j0 = blockIdx.x * 128;

    const int fr = t >> 3;          // 0..63
    const int c8 = t & 7;           // 0..7

    // A row pointers (gathered if requested)
    const float* Agf[4];
    const __half* Agh[4];
    #pragma unroll
    for (int j = 0; j < 4; j++) {
        int r = m0 + fr + 64 * j;
        int ar = (A_F32 && gidx) ? gidx[r] : r;
        if (A_F32) Agf[j] = (const float*)Av + (size_t)ar * Kd + c8 * 8;
        else       Agh[j] = (const __half*)Av + (size_t)ar * Kd + c8 * 8;
    }
    const __half* Wg0 = W + (size_t)(j0 + fr)      * Kd + c8 * 8;
    const __half* Wg1 = W + (size_t)(j0 + fr + 64) * Kd + c8 * 8;
    uint32_t soA[4];
    #pragma unroll
    for (int j = 0; j < 4; j++) soA[j] = (fr + 64 * j) * ROWB + c8 * 16;
    const uint32_t soB0 = fr * ROWB + c8 * 16;
    const uint32_t soB1 = (fr + 64) * ROWB + c8 * 16;

    auto issue_stage = [&](int s, int kt) {
        uint32_t ab_ = sbase + s * STG;
        uint32_t bb_ = ab_ + A_BYTES;
        int ko_ = kt * 64;
        if (A_F32) {
            #pragma unroll
            for (int j = 0; j < 4; j++) {
                float4 u = *(const float4*)(Agf[j] + ko_);
                float4 v = *(const float4*)(Agf[j] + ko_ + 4);
                sts128(ab_ + soA[j],
                       pkh2(u.x, u.y), pkh2(u.z, u.w),
                       pkh2(v.x, v.y), pkh2(v.z, v.w));
            }
        } else {
            #pragma unroll
            for (int j = 0; j < 4; j++)
                cpa16(ab_ + soA[j], Agh[j] + ko_);
        }
        cpa16(bb_ + soB0, Wg0 + ko_);
        cpa16(bb_ + soB1, Wg1 + ko_);
    };

    float acc[4][4][4];
    #pragma unroll
    for (int mt = 0; mt < 4; mt++)
        #pragma unroll
        for (int nt = 0; nt < 4; nt++)
            #pragma unroll
            for (int i = 0; i < 4; i++) acc[mt][nt][i] = 0.f;

    const int iters = Kd >> 6;   // 8 for Kd=512

    issue_stage(0, 0); cpa_commit();
    issue_stage(1, 1); cpa_commit();

    const int a_roff = (lane & 7) + ((lane & 8) ? 8 : 0);
    const int a_cB   = (lane & 16) ? 16 : 0;
    const int b_roff = (lane & 7) + ((lane & 16) ? 8 : 0);
    const int b_cB   = (lane & 8) ? 16 : 0;

    for (int c = 0; c < iters; c++) {
        const int s = c % NSTAGE;
        cpa_wait1();
        __syncthreads();
        if (c + 2 < iters) issue_stage((c + 2) % NSTAGE, c + 2);
        cpa_commit();

        const uint32_t ab = sbase + s * STG;
        const uint32_t bb = ab + A_BYTES;
        #pragma unroll
        for (int ks = 0; ks < 4; ks++) {
            uint32_t bf[4][2];
            #pragma unroll
            for (int ntp = 0; ntp < 2; ntp++) {
                ldsm_x4(bf[2*ntp][0], bf[2*ntp][1], bf[2*ntp+1][0], bf[2*ntp+1][1],
                        bb + (wn * 32 + ntp * 16 + b_roff) * ROWB + ks * 32 + b_cB);
            }
            #pragma unroll
            for (int mt = 0; mt < 4; mt++) {
                uint32_t a0, a1, a2, a3;
                ldsm_x4(a0, a1, a2, a3,
                        ab + (wm * 64 + mt * 16 + a_roff) * ROWB + ks * 32 + a_cB);
                #pragma unroll
                for (int nt = 0; nt < 4; nt++)
                    mma_f16(acc[mt][nt], a0, a1, a2, a3, bf[nt][0], bf[nt][1]);
            }
        }
    }
    __syncthreads();

    const int gr = lane >> 2;
    const int gc = lane & 3;
    #pragma unroll
    for (int mt = 0; mt < 4; mt++) {
        int m_a = m0 + wm * 64 + mt * 16 + gr;
        int m_b = m_a + 8;
        int orow_a = sidx ? sidx[m_a] : m_a;
        int orow_b = sidx ? sidx[m_b] : m_b;
        #pragma unroll
        for (int nt = 0; nt < 4; nt++) {
            int col = j0 + wn * 32 + nt * 8 + gc * 2;
            float b0 = bias[col], b1 = bias[col + 1];
            if (OUT_HALF) {
                __half* out = (__half*)outv;
                *(__half2*)(out + (size_t)orow_a * Ncols + col) =
                    __floats2half2_rn(acc[mt][nt][0] + b0, acc[mt][nt][1] + b1);
                *(__half2*)(out + (size_t)orow_b * Ncols + col) =
                    __floats2half2_rn(acc[mt][nt][2] + b0, acc[mt][nt][3] + b1);
            } else {
                float* out = (float*)outv;
                *(float2*)(out + (size_t)orow_a * Ncols + col) =
                    make_float2(acc[mt][nt][0] + b0, acc[mt][nt][1] + b1);
                *(float2*)(out + (size_t)orow_b * Ncols + col) =
                    make_float2(acc[mt][nt][2] + b0, acc[mt][nt][3] + b1);
            }
        }
    }
}

// ---------------------------------------------------------------------------
// Attention (R12 config — best measured): one block per (patch, head).
// cp.async fill; inline clamp bias; register softmax; ldmatrix.trans PV.
// ---------------------------------------------------------------------------
#define QS0 0                      // 128 rows x 144B
#define KS0 18432
#define VS0 36864
#define CX0 55296
#define CY0 55808
#define CZ0 56320
#define RP0 56832
#define ATTN_SMEM 57344

__global__ __launch_bounds__(256, 2) void attn_kernel(
    const __half* __restrict__ qkv, const int* __restrict__ gcoord,
    const int* __restrict__ order, const float* __restrict__ rpe,
    __half* __restrict__ out, int rpe_num, int pos_b)
{
    extern __shared__ char sm[];
    const uint32_t smb = sptr(sm);
    const int p = blockIdx.x;
    const int h = blockIdx.y;
    const int t = threadIdx.x;
    const int lane = t & 31;
    const int warp = t >> 5;

    int* cx = (int*)(sm + CX0);
    int* cy = (int*)(sm + CY0);
    int* cz = (int*)(sm + CZ0);
    float* rp = (float*)(sm + RP0);

    #pragma unroll
    for (int ii = 0; ii < 4; ii++) {
        int f  = t + ii * 256;
        int i  = f >> 3;
        int hg = (f & 7) * 8;
        const __half* base = qkv + (size_t)(p * 128 + i) * C3 + h * 64 + hg;
        uint32_t dst = i * 144 + hg * 2;
        cpa16(smb + QS0 + dst, base);
        cpa16(smb + KS0 + dst, base + 512);
        cpa16(smb + VS0 + dst, base + 1024);
    }
    cpa_commit();
    if (t < 128) {
        int gi = order[p * 128 + t];
        cx[t] = gcoord[gi * 3 + 0];
        cy[t] = gcoord[gi * 3 + 1];
        cz[t] = gcoord[gi * 3 + 2];
    }
    if (t < 3 * rpe_num) {
        rp[(t / rpe_num) * RPE_MAX + (t % rpe_num)] = rpe[t * H_NUM + h];
    }
    cpa_wait0();
    __syncthreads();

    const int m0w = warp * 16;
    const int a_roff = (lane & 7) + ((lane & 8) ? 8 : 0);
    const int a_cB   = (lane & 16) ? 16 : 0;
    const int b_roff = (lane & 7) + ((lane & 16) ? 8 : 0);
    const int b_cB   = (lane & 8) ? 16 : 0;
    const int gr = lane >> 2;
    const int gc = lane & 3;

    float acc[16][4];
    #pragma unroll
    for (int nt = 0; nt < 16; nt++)
        #pragma unroll
        for (int i = 0; i < 4; i++) acc[nt][i] = 0.f;

    #pragma unroll
    for (int d0 = 0; d0 < 64; d0 += 16) {
        uint32_t a0, a1, a2, a3;
        ldsm_x4(a0, a1, a2, a3,
                smb + QS0 + (m0w + a_roff) * 144 + d0 * 2 + a_cB);
        #pragma unroll
        for (int ntp = 0; ntp < 8; ntp++) {
            uint32_t b0, b1, c0, c1;
            ldsm_x4(b0, b1, c0, c1,
                    smb + KS0 + (ntp * 16 + b_roff) * 144 + d0 * 2 + b_cB);
            mma_f16(acc[2*ntp],     a0, a1, a2, a3, b0, b1);
            mma_f16(acc[2*ntp + 1], a0, a1, a2, a3, c0, c1);
        }
    }

    const float scale = 0.125f;
    const int i0 = m0w + gr, i1 = i0 + 8;
    const int x0 = cx[i0], y0 = cy[i0], z0 = cz[i0];
    const int x1 = cx[i1], y1 = cy[i1], z1 = cz[i1];
    #pragma unroll
    for (int nt = 0; nt < 16; nt++) {
        #pragma unroll
        for (int jj = 0; jj < 2; jj++) {
            int j = nt * 8 + gc * 2 + jj;
            int xj = cx[j], yj = cy[j], zj = cz[j];
            int dx0 = min(max(x0 - xj, -pos_b), pos_b) + pos_b;
            int dy0 = min(max(y0 - yj, -pos_b), pos_b) + pos_b;
            int dz0 = min(max(z0 - zj, -pos_b), pos_b) + pos_b;
            int dx1 = min(max(x1 - xj, -pos_b), pos_b) + pos_b;
            int dy1 = min(max(y1 - yj, -pos_b), pos_b) + pos_b;
            int dz1 = min(max(z1 - zj, -pos_b), pos_b) + pos_b;
            acc[nt][jj]     = acc[nt][jj]     * scale
                            + rp[dx0] + rp[RPE_MAX + dy0] + rp[2*RPE_MAX + dz0];
            acc[nt][jj + 2] = acc[nt][jj + 2] * scale
                            + rp[dx1] + rp[RPE_MAX + dy1] + rp[2*RPE_MAX + dz1];
        }
    }

    float mx0 = -1e30f, mx1 = -1e30f;
    #pragma unroll
    for (int nt = 0; nt < 16; nt++) {
        mx0 = fmaxf(mx0, fmaxf(acc[nt][0], acc[nt][1]));
        mx1 = fmaxf(mx1, fmaxf(acc[nt][2], acc[nt][3]));
    }
    mx0 = fmaxf(mx0, __shfl_xor_sync(0xffffffffu, mx0, 1));
    mx0 = fmaxf(mx0, __shfl_xor_sync(0xffffffffu, mx0, 2));
    mx1 = fmaxf(mx1, __shfl_xor_sync(0xffffffffu, mx1, 1));
    mx1 = fmaxf(mx1, __shfl_xor_sync(0xffffffffu, mx1, 2));

    float s0 = 0.f, s1 = 0.f;
    #pragma unroll
    for (int nt = 0; nt < 16; nt++) {
        acc[nt][0] = __expf(acc[nt][0] - mx0);
        acc[nt][1] = __expf(acc[nt][1] - mx0);
        acc[nt][2] = __expf(acc[nt][2] - mx1);
        acc[nt][3] = __expf(acc[nt][3] - mx1);
        s0 += acc[nt][0] + acc[nt][1];
        s1 += acc[nt][2] + acc[nt][3];
    }
    s0 += __shfl_xor_sync(0xffffffffu, s0, 1);
    s0 += __shfl_xor_sync(0xffffffffu, s0, 2);
    s1 += __shfl_xor_sync(0xffffffffu, s1, 1);
    s1 += __shfl_xor_sync(0xffffffffu, s1, 2);

    float o[8][4];
    #pragma unroll
    for (int nt = 0; nt < 8; nt++)
        #pragma unroll
        for (int i = 0; i < 4; i++) o[nt][i] = 0.f;

    #pragma unroll
    for (int kg = 0; kg < 8; kg++) {
        uint32_t a0 = pkh2(acc[2*kg][0],     acc[2*kg][1]);
        uint32_t a1 = pkh2(acc[2*kg][2],     acc[2*kg][3]);
        uint32_t a2 = pkh2(acc[2*kg + 1][0], acc[2*kg + 1][1]);
        uint32_t a3 = pkh2(acc[2*kg + 1][2], acc[2*kg + 1][3]);
        #pragma unroll
        for (int ntp = 0; ntp < 4; ntp++) {
            uint32_t b0, b1, c0, c1;
            ldsm_x4t(b0, b1, c0, c1,
                     smb + VS0 + (kg * 16 + a_roff) * 144
                               + (ntp * 16 + ((lane & 16) ? 8 : 0)) * 2);
            mma_f16(o[2*ntp],     a0, a1, a2, a3, b0, b1);
            mma_f16(o[2*ntp + 1], a0, a1, a2, a3, c0, c1);
        }
    }

    const float inv0 = 1.f / s0;
    const float inv1 = 1.f / s1;
    #pragma unroll
    for (int nt = 0; nt < 8; nt++) {
        int col = h * 64 + nt * 8 + gc * 2;
        *(__half2*)(out + (size_t)(p * 128 + i0) * C_DIM + col) =
            __floats2half2_rn(o[nt][0] * inv0, o[nt][1] * inv0);
        *(__half2*)(out + (size_t)(p * 128 + i1) * C_DIM + col) =
            __floats2half2_rn(o[nt][2] * inv1, o[nt][3] * inv1);
    }
}

// ---------------------------------------------------------------------------
extern "C" void kernel_launch(void* const* d_in, const int* in_sizes, int n_in,
                              void* d_out, int out_size)
{
    const float* feat   = (const float*)d_in[0];
    const int*   gcoord = (const int*)  d_in[1];
    const int*   order  = (const int*)  d_in[2];
    const float* qkv_w  = (const float*)d_in[4];
    const float* qkv_b  = (const float*)d_in[5];
    const float* proj_w = (const float*)d_in[6];
    const float* proj_b = (const float*)d_in[7];
    const float* rpe    = (const float*)d_in[8];
    float* out = (float*)d_out;

    int rpe_num = in_sizes[8] / (3 * H_NUM);   // 31 (ref comment is wrong)
    if (rpe_num > RPE_MAX) rpe_num = RPE_MAX;
    int pos_b = (rpe_num - 1) / 2;

    __half *qkv_buf = nullptr, *ao_buf = nullptr, *w1 = nullptr, *w3 = nullptr;
    cudaGetSymbolAddress((void**)&qkv_buf, g_qkv);
    cudaGetSymbolAddress((void**)&ao_buf,  g_ao);
    cudaGetSymbolAddress((void**)&w1,      g_w1);
    cudaGetSymbolAddress((void**)&w3,      g_w3);

    cudaFuncSetAttribute((const void*)gemm_h<1, 1>,
                         cudaFuncAttributeMaxDynamicSharedMemorySize, DYN_SMEM);
    cudaFuncSetAttribute((const void*)gemm_h<0, 0>,
                         cudaFuncAttributeMaxDynamicSharedMemorySize, DYN_SMEM);
    cudaFuncSetAttribute(attn_kernel,
                         cudaFuncAttributeMaxDynamicSharedMemorySize, ATTN_SMEM);

    // Pre-pass: weight cvt only (gather fused into stage 1)
    cvt_weights<<<((C3 + C_DIM) * C_DIM / 8) / 256, 256>>>(qkv_w, proj_w, w1, w3);

    // Stage 1: fused gather + QKV projection (fp32 A + gidx, half out)
    dim3 g1(C3 / 128, N_TOT / 256);
    gemm_h<1, 1><<<g1, 512, DYN_SMEM>>>((const void*)feat, w1, qkv_b, qkv_buf,
                                        order, nullptr, C3, C_DIM);

    // Stage 2: attention (half in, half out)
    dim3 ga(P_NUM, H_NUM);
    attn_kernel<<<ga, 256, ATTN_SMEM>>>(qkv_buf, gcoord, order, rpe,
                                        ao_buf, rpe_num, pos_b);

    // Stage 3: output projection + scatter (half in, fp32 out)
    dim3 g3(C_DIM / 128, N_TOT / 256);
    gemm_h<0, 0><<<g3, 512, DYN_SMEM>>>((const void*)ao_buf, w3, proj_b, out,
                                        nullptr, order, C_DIM, C_DIM);
}

// round 17
// speedup vs baseline: 1.0981x; 1.0981x over previous
#include <cuda_runtime.h>
#include <cuda_fp16.h>
#include <stdint.h>

#define N_TOT   131072
#define C_DIM   512
#define H_NUM   8
#define P_NUM   1024
#define C3      1536
#define RPE_MAX 33

static __device__ __half g_qkv [(size_t)N_TOT * C3];     // stage1 out (half)
static __device__ __half g_ao  [(size_t)N_TOT * C_DIM];  // attn out (half)
static __device__ __half g_gath[(size_t)N_TOT * C_DIM];  // feat[order] half
static __device__ __half g_w1  [(size_t)C3 * C_DIM];     // qkv_w half
static __device__ __half g_w3  [(size_t)C_DIM * C_DIM];  // proj_w half

// ---------------------------------------------------------------- helpers --
__device__ __forceinline__ uint32_t sptr(const void* p) {
    return (uint32_t)__cvta_generic_to_shared(p);
}
__device__ __forceinline__ void ldsm_x4(uint32_t& r0, uint32_t& r1,
                                        uint32_t& r2, uint32_t& r3, uint32_t addr) {
    asm volatile("ldmatrix.sync.aligned.m8n8.x4.shared.b16 {%0,%1,%2,%3}, [%4];"
                 : "=r"(r0), "=r"(r1), "=r"(r2), "=r"(r3) : "r"(addr));
}
__device__ __forceinline__ void ldsm_x4t(uint32_t& r0, uint32_t& r1,
                                         uint32_t& r2, uint32_t& r3, uint32_t addr) {
    asm volatile("ldmatrix.sync.aligned.m8n8.x4.trans.shared.b16 {%0,%1,%2,%3}, [%4];"
                 : "=r"(r0), "=r"(r1), "=r"(r2), "=r"(r3) : "r"(addr));
}
__device__ __forceinline__ void mma_f16(float* d,
                                        uint32_t a0, uint32_t a1, uint32_t a2, uint32_t a3,
                                        uint32_t b0, uint32_t b1)
{
    asm volatile(
        "mma.sync.aligned.m16n8k16.row.col.f32.f16.f16.f32 "
        "{%0,%1,%2,%3}, {%4,%5,%6,%7}, {%8,%9}, {%0,%1,%2,%3};"
        : "+f"(d[0]), "+f"(d[1]), "+f"(d[2]), "+f"(d[3])
        : "r"(a0), "r"(a1), "r"(a2), "r"(a3), "r"(b0), "r"(b1));
}
__device__ __forceinline__ uint32_t pkh2(float lo, float hi) {
    __half2 h = __floats2half2_rn(lo, hi);
    return *(uint32_t*)&h;
}
__device__ __forceinline__ void cpa16(uint32_t dst, const void* src) {
    asm volatile("cp.async.cg.shared.global [%0], [%1], 16;"
                 :: "r"(dst), "l"(src) : "memory");
}
__device__ __forceinline__ void cpa_commit() {
    asm volatile("cp.async.commit_group;" ::: "memory");
}
__device__ __forceinline__ void cpa_wait1() {
    asm volatile("cp.async.wait_group 1;" ::: "memory");
}
__device__ __forceinline__ void cpa_wait0() {
    asm volatile("cp.async.wait_group 0;" ::: "memory");
}
__device__ __forceinline__ uint32_t vmax_u16x2(uint32_t a, uint32_t b) {
    uint32_t r;
    asm("max.u16x2 %0, %1, %2;" : "=r"(r) : "r"(a), "r"(b));
    return r;
}
__device__ __forceinline__ uint32_t vmin_u16x2(uint32_t a, uint32_t b) {
    uint32_t r;
    asm("min.u16x2 %0, %1, %2;" : "=r"(r) : "r"(a), "r"(b));
    return r;
}

// ---------------------------------------------------------------------------
// Pre-pass: gather + fp32->fp16 (feat[order] -> g_gath); merged weight cvt
// ---------------------------------------------------------------------------
__global__ __launch_bounds__(256) void gather_cvt(
    const float* __restrict__ feat, const int* __restrict__ order,
    __half* __restrict__ outb)
{
    size_t idx = (size_t)blockIdx.x * 256 + threadIdx.x;  // 8 floats each
    int m = (int)(idx >> 6);
    int c = (int)(idx & 63) << 3;
    int src = order[m];
    const float* fp = feat + (size_t)src * C_DIM + c;
    float4 v0 = *(const float4*)(fp);
    float4 v1 = *(const float4*)(fp + 4);
    __half h[8];
    h[0]=__float2half_rn(v0.x); h[1]=__float2half_rn(v0.y);
    h[2]=__float2half_rn(v0.z); h[3]=__float2half_rn(v0.w);
    h[4]=__float2half_rn(v1.x); h[5]=__float2half_rn(v1.y);
    h[6]=__float2half_rn(v1.z); h[7]=__float2half_rn(v1.w);
    *(uint4*)(outb + idx * 8) = *(uint4*)h;
}

__global__ __launch_bounds__(256) void cvt_weights(
    const float* __restrict__ w1_in, const float* __restrict__ w3_in,
    __half* __restrict__ w1_out, __half* __restrict__ w3_out)
{
    const size_t n1 = (size_t)C3 * C_DIM / 8;
    size_t idx = (size_t)blockIdx.x * 256 + threadIdx.x;
    const float* fp;
    __half* op;
    if (idx < n1) { fp = w1_in + idx * 8; op = w1_out + idx * 8; }
    else          { fp = w3_in + (idx - n1) * 8; op = w3_out + (idx - n1) * 8; }
    float4 v0 = *(const float4*)(fp);
    float4 v1 = *(const float4*)(fp + 4);
    __half h[8];
    h[0]=__float2half_rn(v0.x); h[1]=__float2half_rn(v0.y);
    h[2]=__float2half_rn(v0.z); h[3]=__float2half_rn(v0.w);
    h[4]=__float2half_rn(v1.x); h[5]=__float2half_rn(v1.y);
    h[6]=__float2half_rn(v1.z); h[7]=__float2half_rn(v1.w);
    *(uint4*)op = *(uint4*)h;
}

// ---------------------------------------------------------------------------
// FP16 mma.sync GEMM (NT), fp32 accum (Round-12 config: best measured).
// Block 256m x 128n, BK=64, 512 threads: 16 warps (4m x 4n) of 64x32.
// ---------------------------------------------------------------------------
#define ROWB     144
#define A_BYTES  (256 * ROWB)
#define B_BYTES  (128 * ROWB)
#define STG      (A_BYTES + B_BYTES)
#define NSTAGE   3
#define DYN_SMEM (NSTAGE * STG)           // 165888

template<int OUT_HALF>
__global__ __launch_bounds__(512, 1) void gemm_h(
    const __half* __restrict__ A, const __half* __restrict__ W,
    const float* __restrict__ bias, void* __restrict__ outv,
    const int* __restrict__ sidx, int Ncols, int Kd)
{
    extern __shared__ char dyn[];
    const uint32_t sbase = sptr(dyn);

    const int t = threadIdx.x;
    const int warp = t >> 5;
    const int lane = t & 31;
    const int wm = warp & 3;
    const int wn = warp >> 2;
    const int m0 = blockIdx.y * 256;
    const int j0 = blockIdx.x * 128;

    const int fr = t >> 3;
    const int c8 = t & 7;
    const __half* Ag0 = A + (size_t)(m0 + fr)       * Kd + c8 * 8;
    const __half* Ag1 = A + (size_t)(m0 + fr + 64)  * Kd + c8 * 8;
    const __half* Ag2 = A + (size_t)(m0 + fr + 128) * Kd + c8 * 8;
    const __half* Ag3 = A + (size_t)(m0 + fr + 192) * Kd + c8 * 8;
    const __half* Wg0 = W + (size_t)(j0 + fr)       * Kd + c8 * 8;
    const __half* Wg1 = W + (size_t)(j0 + fr + 64)  * Kd + c8 * 8;
    const uint32_t so0 = fr * ROWB + c8 * 16;
    const uint32_t so1 = (fr + 64)  * ROWB + c8 * 16;
    const uint32_t so2 = (fr + 128) * ROWB + c8 * 16;
    const uint32_t so3 = (fr + 192) * ROWB + c8 * 16;

#define ISSUE_STAGE(s, kt) do {                                   \
        uint32_t ab_ = sbase + (s) * STG;                         \
        uint32_t bb_ = ab_ + A_BYTES;                             \
        int ko_ = (kt) * 64;                                      \
        cpa16(ab_ + so0, Ag0 + ko_);                              \
        cpa16(ab_ + so1, Ag1 + ko_);                              \
        cpa16(ab_ + so2, Ag2 + ko_);                              \
        cpa16(ab_ + so3, Ag3 + ko_);                              \
        cpa16(bb_ + so0, Wg0 + ko_);                              \
        cpa16(bb_ + so1, Wg1 + ko_);                              \
    } while (0)

    float acc[4][4][4];
    #pragma unroll
    for (int mt = 0; mt < 4; mt++)
        #pragma unroll
        for (int nt = 0; nt < 4; nt++)
            #pragma unroll
            for (int i = 0; i < 4; i++) acc[mt][nt][i] = 0.f;

    const int iters = Kd >> 6;

    ISSUE_STAGE(0, 0); cpa_commit();
    ISSUE_STAGE(1, 1); cpa_commit();

    const int a_roff = (lane & 7) + ((lane & 8) ? 8 : 0);
    const int a_cB   = (lane & 16) ? 16 : 0;
    const int b_roff = (lane & 7) + ((lane & 16) ? 8 : 0);
    const int b_cB   = (lane & 8) ? 16 : 0;

    for (int c = 0; c < iters; c++) {
        const int s = c % NSTAGE;
        cpa_wait1();
        __syncthreads();
        if (c + 2 < iters) ISSUE_STAGE((c + 2) % NSTAGE, c + 2);
        cpa_commit();

        const uint32_t ab = sbase + s * STG;
        const uint32_t bb = ab + A_BYTES;
        #pragma unroll
        for (int ks = 0; ks < 4; ks++) {
            uint32_t bf[4][2];
            #pragma unroll
            for (int ntp = 0; ntp < 2; ntp++) {
                ldsm_x4(bf[2*ntp][0], bf[2*ntp][1], bf[2*ntp+1][0], bf[2*ntp+1][1],
                        bb + (wn * 32 + ntp * 16 + b_roff) * ROWB + ks * 32 + b_cB);
            }
            #pragma unroll
            for (int mt = 0; mt < 4; mt++) {
                uint32_t a0, a1, a2, a3;
                ldsm_x4(a0, a1, a2, a3,
                        ab + (wm * 64 + mt * 16 + a_roff) * ROWB + ks * 32 + a_cB);
                #pragma unroll
                for (int nt = 0; nt < 4; nt++)
                    mma_f16(acc[mt][nt], a0, a1, a2, a3, bf[nt][0], bf[nt][1]);
            }
        }
    }
    __syncthreads();

    const int gr = lane >> 2;
    const int gc = lane & 3;
    #pragma unroll
    for (int mt = 0; mt < 4; mt++) {
        int m_a = m0 + wm * 64 + mt * 16 + gr;
        int m_b = m_a + 8;
        int orow_a = sidx ? sidx[m_a] : m_a;
        int orow_b = sidx ? sidx[m_b] : m_b;
        #pragma unroll
        for (int nt = 0; nt < 4; nt++) {
            int col = j0 + wn * 32 + nt * 8 + gc * 2;
            float b0 = bias[col], b1 = bias[col + 1];
            if (OUT_HALF) {
                __half* out = (__half*)outv;
                *(__half2*)(out + (size_t)orow_a * Ncols + col) =
                    __floats2half2_rn(acc[mt][nt][0] + b0, acc[mt][nt][1] + b1);
                *(__half2*)(out + (size_t)orow_b * Ncols + col) =
                    __floats2half2_rn(acc[mt][nt][2] + b0, acc[mt][nt][3] + b1);
            } else {
                float* out = (float*)outv;
                *(float2*)(out + (size_t)orow_a * Ncols + col) =
                    make_float2(acc[mt][nt][0] + b0, acc[mt][nt][1] + b1);
                *(float2*)(out + (size_t)orow_b * Ncols + col) =
                    make_float2(acc[mt][nt][2] + b0, acc[mt][nt][3] + b1);
            }
        }
    }
#undef ISSUE_STAGE
}

// ---------------------------------------------------------------------------
// Attention (R12 + SIMD packed clamps): one block per (patch, head), 8 warps.
// Coords packed x|y<<16; clamp via SWAR sub + min/max.u16x2 (bit-identical).
// ---------------------------------------------------------------------------
#define QS0 0                      // 128 rows x 144B
#define KS0 18432
#define VS0 36864
#define CXY0 55296                 // 128 u32 packed (x | y<<16)
#define CZ0  55808                 // 128 ints
#define RP0  56320                 // 3 x RPE_MAX floats
#define ATTN_SMEM 57344

__global__ __launch_bounds__(256, 2) void attn_kernel(
    const __half* __restrict__ qkv, const int* __restrict__ gcoord,
    const int* __restrict__ order, const float* __restrict__ rpe,
    __half* __restrict__ out, int rpe_num, int pos_b)
{
    extern __shared__ char sm[];
    const uint32_t smb = sptr(sm);
    const int p = blockIdx.x;
    const int h = blockIdx.y;
    const int t = threadIdx.x;
    const int lane = t & 31;
    const int warp = t >> 5;

    uint32_t* cxy = (uint32_t*)(sm + CXY0);
    int* cz = (int*)(sm + CZ0);
    float* rp = (float*)(sm + RP0);

    #pragma unroll
    for (int ii = 0; ii < 4; ii++) {
        int f  = t + ii * 256;
        int i  = f >> 3;
        int hg = (f & 7) * 8;
        const __half* base = qkv + (size_t)(p * 128 + i) * C3 + h * 64 + hg;
        uint32_t dst = i * 144 + hg * 2;
        cpa16(smb + QS0 + dst, base);
        cpa16(smb + KS0 + dst, base + 512);
        cpa16(smb + VS0 + dst, base + 1024);
    }
    cpa_commit();
    if (t < 128) {
        int gi = order[p * 128 + t];
        int x = gcoord[gi * 3 + 0];
        int y = gcoord[gi * 3 + 1];
        cxy[t] = (uint32_t)x | ((uint32_t)y << 16);
        cz[t]  = gcoord[gi * 3 + 2];
    }
    if (t < 3 * rpe_num) {
        rp[(t / rpe_num) * RPE_MAX + (t % rpe_num)] = rpe[t * H_NUM + h];
    }
    cpa_wait0();
    __syncthreads();

    const int m0w = warp * 16;
    const int a_roff = (lane & 7) + ((lane & 8) ? 8 : 0);
    const int a_cB   = (lane & 16) ? 16 : 0;
    const int b_roff = (lane & 7) + ((lane & 16) ? 8 : 0);
    const int b_cB   = (lane & 8) ? 16 : 0;
    const int gr = lane >> 2;
    const int gc = lane & 3;

    float acc[16][4];
    #pragma unroll
    for (int nt = 0; nt < 16; nt++)
        #pragma unroll
        for (int i = 0; i < 4; i++) acc[nt][i] = 0.f;

    #pragma unroll
    for (int d0 = 0; d0 < 64; d0 += 16) {
        uint32_t a0, a1, a2, a3;
        ldsm_x4(a0, a1, a2, a3,
                smb + QS0 + (m0w + a_roff) * 144 + d0 * 2 + a_cB);
        #pragma unroll
        for (int ntp = 0; ntp < 8; ntp++) {
            uint32_t b0, b1, c0, c1;
            ldsm_x4(b0, b1, c0, c1,
                    smb + KS0 + (ntp * 16 + b_roff) * 144 + d0 * 2 + b_cB);
            mma_f16(acc[2*ntp],     a0, a1, a2, a3, b0, b1);
            mma_f16(acc[2*ntp + 1], a0, a1, a2, a3, c0, c1);
        }
    }

    // ---- scale + RPE bias (SWAR clamp; bit-identical to scalar path) ----
    const float scale = 0.125f;
    const int i0 = m0w + gr, i1 = i0 + 8;
    const uint32_t BIAS2 = 0x04000400u;                 // +1024 per half
    const uint32_t lo2 = (uint32_t)(1024 - pos_b) * 0x00010001u;
    const uint32_t hi2 = (uint32_t)(1024 + pos_b) * 0x00010001u;
    const int twop = 2 * pos_b;
    const uint32_t pxy0 = cxy[i0] + BIAS2;
    const uint32_t pxy1 = cxy[i1] + BIAS2;
    const int z0p = cz[i0] + pos_b;
    const int z1p = cz[i1] + pos_b;
    const float* rpy = rp + RPE_MAX;
    const float* rpz = rp + 2 * RPE_MAX;

    #pragma unroll
    for (int nt = 0; nt < 16; nt++) {
        #pragma unroll
        for (int jj = 0; jj < 2; jj++) {
            int j = nt * 8 + gc * 2 + jj;
            uint32_t bj = cxy[j];
            int zj = cz[j];
            uint32_t d0 = vmin_u16x2(vmax_u16x2(pxy0 - bj, lo2), hi2) - lo2;
            uint32_t d1 = vmin_u16x2(vmax_u16x2(pxy1 - bj, lo2), hi2) - lo2;
            int dz0 = min(max(z0p - zj, 0), twop);
            int dz1 = min(max(z1p - zj, 0), twop);
            float bias0 = rp[d0 & 0xFFFF] + rpy[d0 >> 16] + rpz[dz0];
            float bias1 = rp[d1 & 0xFFFF] + rpy[d1 >> 16] + rpz[dz1];
            acc[nt][jj]     = acc[nt][jj]     * scale + bias0;
            acc[nt][jj + 2] = acc[nt][jj + 2] * scale + bias1;
        }
    }

    float mx0 = -1e30f, mx1 = -1e30f;
    #pragma unroll
    for (int nt = 0; nt < 16; nt++) {
        mx0 = fmaxf(mx0, fmaxf(acc[nt][0], acc[nt][1]));
        mx1 = fmaxf(mx1, fmaxf(acc[nt][2], acc[nt][3]));
    }
    mx0 = fmaxf(mx0, __shfl_xor_sync(0xffffffffu, mx0, 1));
    mx0 = fmaxf(mx0, __shfl_xor_sync(0xffffffffu, mx0, 2));
    mx1 = fmaxf(mx1, __shfl_xor_sync(0xffffffffu, mx1, 1));
    mx1 = fmaxf(mx1, __shfl_xor_sync(0xffffffffu, mx1, 2));

    float s0 = 0.f, s1 = 0.f;
    #pragma unroll
    for (int nt = 0; nt < 16; nt++) {
        acc[nt][0] = __expf(acc[nt][0] - mx0);
        acc[nt][1] = __expf(acc[nt][1] - mx0);
        acc[nt][2] = __expf(acc[nt][2] - mx1);
        acc[nt][3] = __expf(acc[nt][3] - mx1);
        s0 += acc[nt][0] + acc[nt][1];
        s1 += acc[nt][2] + acc[nt][3];
    }
    s0 += __shfl_xor_sync(0xffffffffu, s0, 1);
    s0 += __shfl_xor_sync(0xffffffffu, s0, 2);
    s1 += __shfl_xor_sync(0xffffffffu, s1, 1);
    s1 += __shfl_xor_sync(0xffffffffu, s1, 2);

    float o[8][4];
    #pragma unroll
    for (int nt = 0; nt < 8; nt++)
        #pragma unroll
        for (int i = 0; i < 4; i++) o[nt][i] = 0.f;

    #pragma unroll
    for (int kg = 0; kg < 8; kg++) {
        uint32_t a0 = pkh2(acc[2*kg][0],     acc[2*kg][1]);
        uint32_t a1 = pkh2(acc[2*kg][2],     acc[2*kg][3]);
        uint32_t a2 = pkh2(acc[2*kg + 1][0], acc[2*kg + 1][1]);
        uint32_t a3 = pkh2(acc[2*kg + 1][2], acc[2*kg + 1][3]);
        #pragma unroll
        for (int ntp = 0; ntp < 4; ntp++) {
            uint32_t b0, b1, c0, c1;
            ldsm_x4t(b0, b1, c0, c1,
                     smb + VS0 + (kg * 16 + a_roff) * 144
                               + (ntp * 16 + ((lane & 16) ? 8 : 0)) * 2);
            mma_f16(o[2*ntp],     a0, a1, a2, a3, b0, b1);
            mma_f16(o[2*ntp + 1], a0, a1, a2, a3, c0, c1);
        }
    }

    const float inv0 = 1.f / s0;
    const float inv1 = 1.f / s1;
    #pragma unroll
    for (int nt = 0; nt < 8; nt++) {
        int col = h * 64 + nt * 8 + gc * 2;
        *(__half2*)(out + (size_t)(p * 128 + i0) * C_DIM + col) =
            __floats2half2_rn(o[nt][0] * inv0, o[nt][1] * inv0);
        *(__half2*)(out + (size_t)(p * 128 + i1) * C_DIM + col) =
            __floats2half2_rn(o[nt][2] * inv1, o[nt][3] * inv1);
    }
}

// ---------------------------------------------------------------------------
extern "C" void kernel_launch(void* const* d_in, const int* in_sizes, int n_in,
                              void* d_out, int out_size)
{
    const float* feat   = (const float*)d_in[0];
    const int*   gcoord = (const int*)  d_in[1];
    const int*   order  = (const int*)  d_in[2];
    const float* qkv_w  = (const float*)d_in[4];
    const float* qkv_b  = (const float*)d_in[5];
    const float* proj_w = (const float*)d_in[6];
    const float* proj_b = (const float*)d_in[7];
    const float* rpe    = (const float*)d_in[8];
    float* out = (float*)d_out;

    int rpe_num = in_sizes[8] / (3 * H_NUM);   // 31 (ref comment is wrong)
    if (rpe_num > RPE_MAX) rpe_num = RPE_MAX;
    int pos_b = (rpe_num - 1) / 2;

    __half *qkv_buf = nullptr, *ao_buf = nullptr, *gath = nullptr,
           *w1 = nullptr, *w3 = nullptr;
    cudaGetSymbolAddress((void**)&qkv_buf, g_qkv);
    cudaGetSymbolAddress((void**)&ao_buf,  g_ao);
    cudaGetSymbolAddress((void**)&gath,    g_gath);
    cudaGetSymbolAddress((void**)&w1,      g_w1);
    cudaGetSymbolAddress((void**)&w3,      g_w3);

    cudaFuncSetAttribute(gemm_h<1>,
                         cudaFuncAttributeMaxDynamicSharedMemorySize, DYN_SMEM);
    cudaFuncSetAttribute(gemm_h<0>,
                         cudaFuncAttributeMaxDynamicSharedMemorySize, DYN_SMEM);
    cudaFuncSetAttribute(attn_kernel,
                         cudaFuncAttributeMaxDynamicSharedMemorySize, ATTN_SMEM);

    // Pre-pass: gather+cvt feat; both weight cvts in one launch
    gather_cvt<<<(N_TOT * (C_DIM / 8)) / 256, 256>>>(feat, order, gath);
    cvt_weights<<<((C3 + C_DIM) * C_DIM / 8) / 256, 256>>>(qkv_w, proj_w, w1, w3);

    // Stage 1: QKV projection (fp16 in, half out)
    dim3 g1(C3 / 128, N_TOT / 256);
    gemm_h<1><<<g1, 512, DYN_SMEM>>>(gath, w1, qkv_b, qkv_buf, nullptr,
                                     C3, C_DIM);

    // Stage 2: attention (half in, half out)
    dim3 ga(P_NUM, H_NUM);
    attn_kernel<<<ga, 256, ATTN_SMEM>>>(qkv_buf, gcoord, order, rpe,
                                        ao_buf, rpe_num, pos_b);

    // Stage 3: output projection + scatter (half in, fp32 out)
    dim3 g3(C_DIM / 128, N_TOT / 256);
    gemm_h<0><<<g3, 512, DYN_SMEM>>>(ao_buf, w3, proj_b, out, order,
                                     C_DIM, C_DIM);
}